// round 14
// baseline (speedup 1.0000x reference)
#include <cuda_runtime.h>
#include <cuda_bf16.h>
#include <cstdint>

#define NNODES 20000
#define NEDGES 640000
#define IND    256
#define HID    128
#define NG     64

#define KBLK   139          // CTAs in split-K GEMM
#define KPADB  140          // padded partial count (index 139 stays zero forever)
#define NB     144          // nodes per CTA
#define NST    9            // stages of 16 nodes
#define TCTA   128          // tail_k CTAs

// ---------------- device scratch (zero-initialized at module load) ----------------
__device__ __align__(16) unsigned g_Cp[NNODES * 16];       // packed u8 counts [node][g]
__device__ __align__(16) int      g_outdeg[NNODES];
__device__ __align__(16) float    g_cntF[NG];              // per-graph edge counts (col sums of C)
__device__ __align__(16) float    g_part[KPADB][128][IND]; // split-K partials
__device__ __align__(16) float    g_XF[128][IND];          // pooled features
__device__ __align__(16) float    g_P[2][128][HID];        // layer activations
__device__ volatile unsigned      g_tbar[4];               // tail barriers (reset by mm_k)

// ---------------- helpers ----------------
__device__ __forceinline__ uint32_t f2tf32(float v) {
    uint32_t t;
    asm("cvt.rna.tf32.f32 %0, %1;" : "=r"(t) : "f"(v));
    return t;
}
__device__ __forceinline__ void mma_tf32(float* d, uint32_t a0, uint32_t a1, uint32_t a2,
                                         uint32_t a3, uint32_t b0, uint32_t b1) {
    asm volatile(
        "mma.sync.aligned.m16n8k8.row.col.f32.tf32.tf32.f32 "
        "{%0,%1,%2,%3},{%4,%5,%6,%7},{%8,%9},{%0,%1,%2,%3};"
        : "+f"(d[0]), "+f"(d[1]), "+f"(d[2]), "+f"(d[3])
        : "r"(a0), "r"(a1), "r"(a2), "r"(a3), "r"(b0), "r"(b1));
}
// B smem layout (verified R9): element (k, n) of the 16x256 x-tile
__device__ __forceinline__ uint32_t bofB(int k, int n) {
    int nq  = n & 7;
    int nb  = n >> 3;
    int blk = ((nb >> 2) ^ nq ^ ((k & 3) << 1)) & 7;
    return (uint32_t)(k * 1024 + nq * 128 + blk * 16 + (nb & 3) * 4);
}
// A smem layout (verified R9): transposed [k][m]
__device__ __forceinline__ uint32_t bofA(int k, int m) {
    int mb  = m >> 2;
    int blk = (mb & 24) | (((mb & 7) ^ ((k & 3) << 1)) & 7);
    return (uint32_t)(k * 512 + blk * 16 + (m & 3) * 4);
}

// ---------------- kernels ----------------
// 8 edges per thread, 2 global REDs per edge; no histogram (cnt derived in mm_k)
__global__ void count_k(const int* __restrict__ src, const int* __restrict__ dst,
                        const int* __restrict__ batch) {
    int t   = threadIdx.x;
    int gid = blockIdx.x * blockDim.x + t;     // one thread = 8 edges
    if (blockIdx.x == 0 && t < NG) g_cntF[t] = 0.f;   // reset for mm_k accumulation
    if (gid < NEDGES / 8) {
        int4 s0 = ((const int4*)src)[gid * 2];
        int4 s1 = ((const int4*)src)[gid * 2 + 1];
        int4 d0 = ((const int4*)dst)[gid * 2];
        int4 d1 = ((const int4*)dst)[gid * 2 + 1];
        int ss[8] = {s0.x, s0.y, s0.z, s0.w, s1.x, s1.y, s1.z, s1.w};
        int dd[8] = {d0.x, d0.y, d0.z, d0.w, d1.x, d1.y, d1.z, d1.w};
        int gg[8];
#pragma unroll
        for (int u = 0; u < 8; u++) gg[u] = batch[ss[u]];   // 8 independent gathers
#pragma unroll
        for (int u = 0; u < 8; u++)
            atomicAdd(&g_Cp[dd[u] * 16 + (gg[u] >> 2)], 1u << ((gg[u] & 3) * 8));
#pragma unroll
        for (int u = 0; u < 8; u++) atomicAdd(&g_outdeg[ss[u]], 1);
    }
}

// TF32 pooling GEMM (verified R9) + cnt column-sum + self-cleaning epilogue
__global__ void __launch_bounds__(512, 1) mm_k(const float* __restrict__ x,
                                               const int* __restrict__ batch) {
    __shared__ __align__(16) float Bsm[2][16 * 256];
    __shared__ __align__(16) float Atr[2][16 * 128];

    const uint8_t* C8 = (const uint8_t*)g_Cp;
    int b    = blockIdx.x;
    int n0   = b * NB;
    int tid  = threadIdx.x;
    int lane = tid & 31;
    int warp = tid >> 5;
    int wm   = warp & 7;
    int wn   = warp >> 3;
    int kq   = lane & 3;
    int r8   = lane >> 2;

    int kx = warp;
    int cx = lane;
    int ma = tid & 127;
    int kh = tid >> 7;

    float acc[16][4];
#pragma unroll
    for (int i = 0; i < 16; i++)
#pragma unroll
        for (int j = 0; j < 4; j++) acc[i][j] = 0.f;

    const float4* x4 = (const float4*)x;

    float4 pv0, pv1;
    float  pa[4];
    float  csum = 0.f;     // running column sum of C (rows ma<NG only)
    auto prefetch = [&](int s) {
        int nx = n0 + s * 16 + kx;
        if (nx < NNODES) {
            pv0 = x4[(size_t)nx * 64 + cx * 2];
            pv1 = x4[(size_t)nx * 64 + cx * 2 + 1];
        } else {
            pv0 = make_float4(0.f, 0.f, 0.f, 0.f);
            pv1 = pv0;
        }
#pragma unroll
        for (int j = 0; j < 4; j++) {
            int na = n0 + s * 16 + kh * 4 + j;
            float v = 0.f;
            if (na < NNODES) {
                if (ma < NG) {
                    v = (float)C8[na * 64 + ma];
                } else {
                    int g = ma - NG;
                    if (batch[na] == g) v = (float)g_outdeg[na];
                }
            }
            pa[j] = v;
        }
        if (ma < NG) csum += (pa[0] + pa[1]) + (pa[2] + pa[3]);
    };
    auto stage = [&](int buf) {
        float vs[8] = {pv0.x, pv0.y, pv0.z, pv0.w, pv1.x, pv1.y, pv1.z, pv1.w};
        char* Bb = (char*)Bsm[buf];
        char* Ab = (char*)Atr[buf];
#pragma unroll
        for (int j = 0; j < 8; j++)
            *(uint32_t*)(Bb + bofB(kx, cx * 8 + j)) = f2tf32(vs[j]);
#pragma unroll
        for (int j = 0; j < 4; j++)
            *(uint32_t*)(Ab + bofA(kh * 4 + j, ma)) = f2tf32(pa[j]);
    };

    prefetch(0);
    stage(0);

    for (int s = 0; s < NST; s++) {
        __syncthreads();
        int buf = s & 1;
        if (s + 1 < NST) prefetch(s + 1);

        const char* Ab = (const char*)Atr[buf];
        const char* Bb = (const char*)Bsm[buf];
#pragma unroll
        for (int ko = 0; ko < 16; ko += 8) {
            uint32_t a0 = *(const uint32_t*)(Ab + bofA(ko + kq,     wm * 16 + r8));
            uint32_t a1 = *(const uint32_t*)(Ab + bofA(ko + kq,     wm * 16 + r8 + 8));
            uint32_t a2 = *(const uint32_t*)(Ab + bofA(ko + 4 + kq, wm * 16 + r8));
            uint32_t a3 = *(const uint32_t*)(Ab + bofA(ko + 4 + kq, wm * 16 + r8 + 8));
#pragma unroll
            for (int g0 = 0; g0 < 4; g0++) {
                int nbase = (wn * 16 + g0 * 4) * 8 + r8;
                float4 f0 = *(const float4*)(Bb + bofB(ko + kq,     nbase));
                float4 f1 = *(const float4*)(Bb + bofB(ko + 4 + kq, nbase));
                const float b0v[4] = {f0.x, f0.y, f0.z, f0.w};
                const float b1v[4] = {f1.x, f1.y, f1.z, f1.w};
#pragma unroll
                for (int t = 0; t < 4; t++) {
                    mma_tf32(acc[g0 * 4 + t], a0, a1, a2, a3,
                             __float_as_uint(b0v[t]), __float_as_uint(b1v[t]));
                }
            }
        }
        if (s + 1 < NST) stage((s + 1) & 1);
    }

    int r0 = wm * 16 + r8;
    int c0 = wn * 128 + kq * 2;
#pragma unroll
    for (int nb = 0; nb < 16; nb++) {
        int c = c0 + nb * 8;
        *(float2*)&g_part[b][r0][c]     = make_float2(acc[nb][0], acc[nb][1]);
        *(float2*)&g_part[b][r0 + 8][c] = make_float2(acc[nb][2], acc[nb][3]);
    }

    // cnt column-sum contribution (integer-valued floats: order-independent)
    if (ma < NG) atomicAdd(&g_cntF[ma], csum);

    // ---- self-clean: zero OWN disjoint slice of counts/outdeg for next call ----
    uint4 zu = make_uint4(0u, 0u, 0u, 0u);
    for (int i = tid; i < NB * 4; i += 512) {
        int n = n0 + (i >> 2);
        if (n < NNODES) ((uint4*)g_Cp)[n * 4 + (i & 3)] = zu;
    }
    for (int i = tid; i < NB; i += 512) {
        int n = n0 + i;
        if (n < NNODES) g_outdeg[n] = 0;
    }
    if (b == 0 && tid >= 64 && tid < 68) g_tbar[tid - 64] = 0u;   // reset tail barriers
}

// tail: fold partials -> XF (float4, 4-way depth split), then 3 head layers
__global__ void __launch_bounds__(256, 1)
tail_k(const float* __restrict__ W0, const float* __restrict__ b0p,
       const float* __restrict__ W1, const float* __restrict__ b1p,
       const float* __restrict__ W2, const float* __restrict__ b2p,
       float* __restrict__ out) {
    __shared__ float As[16][17];
    __shared__ float Ws[16][17];
    __shared__ float4 red[4][64];
    int b   = blockIdx.x;
    int tid = threadIdx.x;

    auto gbar = [&](int i) {
        __syncthreads();
        __threadfence();
        if (tid == 0) {
            atomicAdd((unsigned*)&g_tbar[i], 1u);
            while (g_tbar[i] < (unsigned)TCTA) { }
        }
        __syncthreads();
        __threadfence();
    };

    // ---- phase 0: fold 140 partials for row m=b (float4, depth quarters of 35) ----
    {
        int m  = b;
        int f4 = tid & 63;      // float4 column group
        int qq = tid >> 6;      // depth quarter 0..3
        const float4* p = (const float4*)&g_part[qq * 35][m][f4 * 4];
        const size_t stride4 = (size_t)128 * IND / 4;     // float4s between partials
        float4 acc = make_float4(0.f, 0.f, 0.f, 0.f);
#pragma unroll
        for (int q0 = 0; q0 < 35; q0 += 7) {
            float4 v[7];
#pragma unroll
            for (int q = 0; q < 7; q++) v[q] = p[(size_t)(q0 + q) * stride4];
#pragma unroll
            for (int q = 0; q < 7; q++) {
                acc.x += v[q].x; acc.y += v[q].y; acc.z += v[q].z; acc.w += v[q].w;
            }
        }
        red[qq][f4] = acc;
        __syncthreads();
        if (qq == 0) {
            float4 a0 = red[0][f4], a1 = red[1][f4], a2 = red[2][f4], a3 = red[3][f4];
            float4 s;
            s.x = (a0.x + a1.x) + (a2.x + a3.x);
            s.y = (a0.y + a1.y) + (a2.y + a3.y);
            s.z = (a0.z + a1.z) + (a2.z + a3.z);
            s.w = (a0.w + a1.w) + (a2.w + a3.w);
            int g = m & (NG - 1);
            float cnt = g_cntF[g];
            float inv = cnt > 0.5f ? 1.0f / cnt : 0.0f;
            s.x *= inv; s.y *= inv; s.z *= inv; s.w *= inv;
            int row = (m < NG) ? (NG + m) : (m - NG);   // dst -> 64.., src -> 0..
            ((float4*)&g_XF[row][0])[f4] = s;
        }
    }
    gbar(0);

    // ---- phases 1-3: head layers (64 CTAs active) ----
#pragma unroll
    for (int layer = 0; layer < 3; layer++) {
        if (b < 64) {
            int rt = b >> 3, ct = b & 7;
            int ty = tid >> 4, tx = tid & 15;
            int r  = rt * 16 + ty;
            int c  = ct * 16 + tx;
            const float* A  = (layer == 0) ? &g_XF[0][0]
                             : (layer == 1) ? &g_P[0][0][0] : &g_P[1][0][0];
            const float* W  = (layer == 0) ? W0 : (layer == 1) ? W1 : W2;
            const float* bs = (layer == 0) ? b0p : (layer == 1) ? b1p : b2p;
            int K = (layer == 0) ? IND : HID;
            float acc = 0.f;
            for (int k0 = 0; k0 < K; k0 += 16) {
                As[ty][tx] = A[r * K + k0 + tx];
                Ws[ty][tx] = W[(k0 + ty) * HID + c];
                __syncthreads();
#pragma unroll
                for (int kk = 0; kk < 16; kk++) acc += As[ty][kk] * Ws[kk][tx];
                __syncthreads();
            }
            int g = r & (NG - 1);
            float flag = g_cntF[g] > 0.5f ? 1.0f : 0.0f;
            float v = (acc + bs[c]) * flag;
            if (layer < 2) g_P[layer][r][c] = v;
            int col = layer * 256 + ((r < NG) ? 0 : HID) + c;
            out[g * 768 + col] = v;
        }
        if (layer < 2) gbar(layer + 1);
    }
}

// ---------------- launcher ----------------
extern "C" void kernel_launch(void* const* d_in, const int* in_sizes, int n_in,
                              void* d_out, int out_size) {
    const float* x     = (const float*)d_in[0];
    const int*   eidx  = (const int*)d_in[1];
    const int*   batch = (const int*)d_in[2];
    const float* W0 = (const float*)d_in[3];
    const float* b0 = (const float*)d_in[4];
    const float* W1 = (const float*)d_in[5];
    const float* b1 = (const float*)d_in[6];
    const float* W2 = (const float*)d_in[7];
    const float* b2 = (const float*)d_in[8];
    float* out = (float*)d_out;

    const int* src = eidx;
    const int* dst = eidx + NEDGES;

    count_k<<<(NEDGES / 8 + 255) / 256, 256>>>(src, dst, batch);
    mm_k<<<KBLK, 512>>>(x, batch);
    tail_k<<<TCTA, 256>>>(W0, b0, W1, b1, W2, b2, out);
}